// round 1
// baseline (speedup 1.0000x reference)
#include <cuda_runtime.h>

// Problem constants
#define BB 16
#define CC 12
#define MM 384
#define NN 384

#define TILE 64
#define HALO 8
#define SDIM (TILE + 2 * HALO)   // 80
#define NTHREADS 256

__global__ void wa_zero_kernel(float* __restrict__ out, int n) {
    int i = blockIdx.x * blockDim.x + threadIdx.x;
    if (i < n) out[i] = 0.0f;
}

__global__ __launch_bounds__(NTHREADS)
void wa_scatter_kernel(const float* __restrict__ x,
                       const float* __restrict__ u,
                       float* __restrict__ out)
{
    __shared__ float acc[SDIM * SDIM];

    const int tx0 = blockIdx.x * TILE;   // tile origin col
    const int ty0 = blockIdx.y * TILE;   // tile origin row
    const int b   = blockIdx.z;
    const int t   = threadIdx.x;

    // zero shared accumulator
    #pragma unroll
    for (int k = t; k < SDIM * SDIM; k += NTHREADS) acc[k] = 0.0f;
    __syncthreads();

    float* __restrict__ outb = out + (size_t)b * MM * NN;

    const int lx = t & (TILE - 1);        // 0..63 -> coalesced along j
    const int ly0 = t >> 6;               // 0..3
    const int j  = tx0 + lx;

    for (int c = 0; c < CC; ++c) {
        const size_t plane = ((size_t)b * CC + c) * (size_t)(MM * NN);
        const float*  __restrict__ xp = x + plane;
        const float2* __restrict__ up = reinterpret_cast<const float2*>(u) + plane;

        #pragma unroll 4
        for (int ly = ly0; ly < TILE; ly += NTHREADS / TILE) {
            const int i = ty0 + ly;
            const size_t idx = (size_t)i * NN + j;
            const float  xv = xp[idx];
            const float2 uv = up[idx];     // uv.x = col disp, uv.y = row disp

            const float tcx = (float)j + uv.x;
            const float tcy = (float)i + uv.y;
            const float fx = floorf(tcx);
            const float fy = floorf(tcy);
            const float wx = tcx - fx;
            const float wy = tcy - fy;
            const int x0 = (int)fx;
            const int y0 = (int)fy;

            const float omwx = 1.0f - wx;
            const float omwy = 1.0f - wy;
            const float w00 = omwy * omwx * xv;
            const float w01 = omwy * wx   * xv;
            const float w10 = wy   * omwx * xv;
            const float w11 = wy   * wx   * xv;

            const int sx = x0 - tx0 + HALO;
            const int sy = y0 - ty0 + HALO;

            if ((unsigned)sx <= (unsigned)(SDIM - 2) &&
                (unsigned)sy <= (unsigned)(SDIM - 2)) {
                float* p = acc + sy * SDIM + sx;
                atomicAdd(p,            w00);
                atomicAdd(p + 1,        w01);
                atomicAdd(p + SDIM,     w10);
                atomicAdd(p + SDIM + 1, w11);
            } else {
                // Rare fallback (|u| > HALO-1): scatter straight to global
                // with the reference's zero-padding (drop OOB) convention.
                #pragma unroll
                for (int dy = 0; dy < 2; ++dy) {
                    #pragma unroll
                    for (int dx = 0; dx < 2; ++dx) {
                        const int yy = y0 + dy;
                        const int xx = x0 + dx;
                        if ((unsigned)yy < (unsigned)MM &&
                            (unsigned)xx < (unsigned)NN) {
                            const float w = (dy ? wy : omwy) * (dx ? wx : omwx) * xv;
                            atomicAdd(outb + (size_t)yy * NN + xx, w);
                        }
                    }
                }
            }
        }
    }

    __syncthreads();

    // Flush shared tile (with halo) to global via RED atomics; drop OOB cells.
    #pragma unroll
    for (int k = t; k < SDIM * SDIM; k += NTHREADS) {
        const float v = acc[k];
        if (v != 0.0f) {
            const int sy = k / SDIM;
            const int sx = k - sy * SDIM;
            const int gy = ty0 + sy - HALO;
            const int gx = tx0 + sx - HALO;
            if ((unsigned)gy < (unsigned)MM && (unsigned)gx < (unsigned)NN)
                atomicAdd(outb + (size_t)gy * NN + gx, v);
        }
    }
}

extern "C" void kernel_launch(void* const* d_in, const int* in_sizes, int n_in,
                              void* d_out, int out_size) {
    const float* x = (const float*)d_in[0];
    const float* u = (const float*)d_in[1];
    float* out = (float*)d_out;

    // out is poisoned; zero it first.
    wa_zero_kernel<<<(out_size + 255) / 256, 256>>>(out, out_size);

    dim3 grid(NN / TILE, MM / TILE, BB);   // 6 x 6 x 16 = 576 CTAs
    wa_scatter_kernel<<<grid, NTHREADS>>>(x, u, out);
}